// round 12
// baseline (speedup 1.0000x reference)
#include <cuda_runtime.h>
#include <cuda_fp16.h>
#include <math.h>
#include <stdint.h>

#define NT 128
#define BUF 8192                       // one 64x64 fp16 buffer: 64 rows x 128B
#define SMEM_TOTAL (6*BUF + 64)
// buffer roles: 0,1 = Y splits ; 2,3 = Z splits ; 4,5 = T/A splits

__device__ __forceinline__ uint32_t swz(uint32_t b) { return b ^ ((b >> 3) & 0x70); }

__device__ __forceinline__ uint32_t smem_u32(const void* p) {
    uint32_t a;
    asm("{ .reg .u64 t; cvta.to.shared.u64 t, %1; cvt.u32.u64 %0, t; }" : "=r"(a) : "l"(p));
    return a;
}

__device__ __forceinline__ void ldsm4(uint32_t* r, uint32_t addr) {
    asm volatile("ldmatrix.sync.aligned.m8n8.x4.shared.b16 {%0,%1,%2,%3}, [%4];"
                 : "=r"(r[0]), "=r"(r[1]), "=r"(r[2]), "=r"(r[3]) : "r"(addr));
}

__device__ __forceinline__ void mma16816(float* c, const uint32_t* a,
                                         uint32_t b0, uint32_t b1) {
    asm volatile("mma.sync.aligned.m16n8k16.row.col.f32.f16.f16.f32 "
                 "{%0,%1,%2,%3}, {%4,%5,%6,%7}, {%8,%9}, {%0,%1,%2,%3};"
                 : "+f"(c[0]), "+f"(c[1]), "+f"(c[2]), "+f"(c[3])
                 : "r"(a[0]), "r"(a[1]), "r"(a[2]), "r"(a[3]), "r"(b0), "r"(b1));
}

// fp32 -> 2-term fp16 split
__device__ __forceinline__ void split2(float v, __half& h1, __half& h2) {
    h1 = __float2half_rn(v);
    h2 = __float2half_rn(v - __half2float(h1));
}
__device__ __forceinline__ uint32_t packh(__half a, __half b) {
    __half2 t; t.x = a; t.y = b;
    return *reinterpret_cast<uint32_t*>(&t);
}

// ---- epilogue: transform, split, store. No barriers inside. ----
// MODE 0: dst = D   MODE 1: dst = 1.5I - 0.5 D   MODE 2: gmem O = scale*D
template <int MODE>
__device__ __forceinline__ void epi_phase(char* smem, int d1, int d2,
                                          float* __restrict__ O, float scale,
                                          int wm, int wn, int lane,
                                          const float acc[2][4][4])
{
    const int gr = lane >> 2, qp = lane & 3;
#pragma unroll
    for (int mt = 0; mt < 2; ++mt)
#pragma unroll
    for (int j = 0; j < 4; ++j) {
        const int colb = wn * 32 + j * 8 + 2 * qp;
#pragma unroll
        for (int half = 0; half < 2; ++half) {
            const int row = wm * 32 + mt * 16 + gr + half * 8;
            float v0 = acc[mt][j][half * 2 + 0];
            float v1 = acc[mt][j][half * 2 + 1];
            if (MODE == 1) {
                v0 = (colb     == row ? 1.5f : 0.0f) - 0.5f * v0;
                v1 = (colb + 1 == row ? 1.5f : 0.0f) - 0.5f * v1;
            }
            if (MODE == 2) {
                *(float2*)(O + row * 64 + colb) = make_float2(v0 * scale, v1 * scale);
            } else {
                __half p0, q0, p1, q1;
                split2(v0, p0, q0);
                split2(v1, p1, q1);
                uint32_t off = swz((uint32_t)(row * 128 + colb * 2));
                *(uint32_t*)(smem + d1 + off) = packh(p0, p1);
                *(uint32_t*)(smem + d2 + off) = packh(q0, q1);
            }
        }
    }
}

// ---- disjoint GEMM: dest buffers intersect no source buffer ----
// Single opening barrier; epilogue overlaps other warps' MMA freely.
template <int MODE>
__device__ __forceinline__ void gemm_disjoint(uint32_t sbase, char* smem,
                                              int a1, int a2, int b1, int b2,
                                              int d1, int d2,
                                              float* __restrict__ O, float scale,
                                              int wm, int wn, int lane)
{
    __syncthreads();   // previous epilogue writes visible

    float acc[2][4][4];
#pragma unroll
    for (int mt = 0; mt < 2; ++mt)
#pragma unroll
        for (int j = 0; j < 4; ++j)
#pragma unroll
            for (int q = 0; q < 4; ++q) acc[mt][j][q] = 0.0f;

    const int arow = wm * 32 + (lane & 15);
    const int acol = (lane >> 4) * 16;
    const int bl = lane & 7;
    const int bg = lane >> 3;
    const uint32_t bcol = (uint32_t)((bg >> 1) * 32 + (bg & 1) * 16);

#pragma unroll
    for (int ktp = 0; ktp < 2; ++ktp) {
        uint32_t A1[2][2][4], A2[2][2][4];
#pragma unroll
        for (int mt = 0; mt < 2; ++mt)
#pragma unroll
            for (int ktl = 0; ktl < 2; ++ktl) {
                uint32_t rel = swz((uint32_t)((arow + mt * 16) * 128 +
                                              ktp * 64 + ktl * 32 + acol));
                ldsm4(A1[mt][ktl], sbase + a1 + rel);
                ldsm4(A2[mt][ktl], sbase + a2 + rel);
            }
#pragma unroll
        for (int j = 0; j < 4; ++j) {
            const uint32_t rowb = (uint32_t)((wn * 32 + j * 8 + bl) * 128);
            uint32_t rel = swz(rowb + ktp * 64 + bcol);
            uint32_t Bx[4], Cx[4];
            ldsm4(Bx, sbase + b1 + rel);
            ldsm4(Cx, sbase + b2 + rel);
#pragma unroll
            for (int ktl = 0; ktl < 2; ++ktl) {
#pragma unroll
                for (int mt = 0; mt < 2; ++mt) {
                    mma16816(acc[mt][j], A1[mt][ktl], Bx[2*ktl], Bx[2*ktl+1]);
                    mma16816(acc[mt][j], A1[mt][ktl], Cx[2*ktl], Cx[2*ktl+1]);
                    mma16816(acc[mt][j], A2[mt][ktl], Bx[2*ktl], Bx[2*ktl+1]);
                }
            }
        }
    }
    // no mid-barrier: dest disjoint from all sources
    epi_phase<MODE>(smem, d1, d2, O, scale, wm, wn, lane, acc);
}

// ---- in-place GEMM: dest pair == A-side source pair (D = Asrc @ B) ----
// A-side reads are row-partitioned by wm and the warp writes its own wm rows,
// so the only race is within a wm-pair: load ALL A-frags first, then a
// 64-thread named barrier, then B+MMA+epilogue with no further sync.
__device__ __forceinline__ void gemm_inplace(uint32_t sbase, char* smem,
                                             int a1, int a2, int b1, int b2,
                                             int wm, int wn, int lane)
{
    __syncthreads();   // previous epilogue writes visible

    const int arow = wm * 32 + (lane & 15);
    const int acol = (lane >> 4) * 16;

    // all A fragments up front (the in-place buffer is fully read here)
    uint32_t A1[2][2][2][4], A2[2][2][2][4];   // [ktp][mt][ktl]
#pragma unroll
    for (int ktp = 0; ktp < 2; ++ktp)
#pragma unroll
        for (int mt = 0; mt < 2; ++mt)
#pragma unroll
            for (int ktl = 0; ktl < 2; ++ktl) {
                uint32_t rel = swz((uint32_t)((arow + mt * 16) * 128 +
                                              ktp * 64 + ktl * 32 + acol));
                ldsm4(A1[ktp][mt][ktl], sbase + a1 + rel);
                ldsm4(A2[ktp][mt][ktl], sbase + a2 + rel);
            }

    // pair-local barrier: warps 0,1 = threads 0-63 (wm=0), warps 2,3 = 64-127
    asm volatile("bar.sync %0, 64;" :: "r"(1 + wm));

    float acc[2][4][4];
#pragma unroll
    for (int mt = 0; mt < 2; ++mt)
#pragma unroll
        for (int j = 0; j < 4; ++j)
#pragma unroll
            for (int q = 0; q < 4; ++q) acc[mt][j][q] = 0.0f;

    const int bl = lane & 7;
    const int bg = lane >> 3;
    const uint32_t bcol = (uint32_t)((bg >> 1) * 32 + (bg & 1) * 16);

#pragma unroll
    for (int ktp = 0; ktp < 2; ++ktp) {
#pragma unroll
        for (int j = 0; j < 4; ++j) {
            const uint32_t rowb = (uint32_t)((wn * 32 + j * 8 + bl) * 128);
            uint32_t rel = swz(rowb + ktp * 64 + bcol);
            uint32_t Bx[4], Cx[4];
            ldsm4(Bx, sbase + b1 + rel);
            ldsm4(Cx, sbase + b2 + rel);
#pragma unroll
            for (int ktl = 0; ktl < 2; ++ktl) {
#pragma unroll
                for (int mt = 0; mt < 2; ++mt) {
                    mma16816(acc[mt][j], A1[ktp][mt][ktl], Bx[2*ktl], Bx[2*ktl+1]);
                    mma16816(acc[mt][j], A1[ktp][mt][ktl], Cx[2*ktl], Cx[2*ktl+1]);
                    mma16816(acc[mt][j], A2[ktp][mt][ktl], Bx[2*ktl], Bx[2*ktl+1]);
                }
            }
        }
    }
    // epilogue writes back into the A-source pair (own wm rows only)
    epi_phase<0>(smem, a1, a2, (float*)nullptr, 0.f, wm, wn, lane, acc);
}

__global__ void __launch_bounds__(NT, 4)
isqrtm_hmma_kernel(const float* __restrict__ x, float* __restrict__ out)
{
    extern __shared__ char smem[];
    const uint32_t sbase = smem_u32(smem);
    float* red = (float*)(smem + 6 * BUF);

    const int tid = threadIdx.x;
    const int wid = tid >> 5, lane = tid & 31;
    const int wm = wid >> 1, wn = wid & 1;
    const int b = blockIdx.x;
    const float* X = x + (size_t)b * 4096;
    float* O = out + (size_t)b * 4096;

    // ---- trace(X) ----
    float tr = (tid < 64) ? __ldg(X + tid * 65) : 0.0f;
#pragma unroll
    for (int o = 16; o; o >>= 1) tr += __shfl_xor_sync(0xFFFFFFFFu, tr, o);
    if (lane == 0) red[wid] = tr;
    __syncthreads();
    const float normA = red[0] + red[1];
    const float inv = 1.0f / normA;
    const float sq  = sqrtf(normA);
    __syncthreads();

    // ---- prologue: A = X/normA -> bufs 4,5 ; Z = 1.5I - 0.5A -> bufs 2,3 ----
    {
        const int r  = tid >> 1;
        const int c0 = (tid & 1) * 32;
#pragma unroll
        for (int q = 0; q < 16; ++q) {
            const int c = c0 + 2 * q;
            float2 f = *(const float2*)(X + r * 64 + c);
            float a0 = f.x * inv, a1 = f.y * inv;
            float z0 = (c     == r ? 1.5f : 0.0f) - 0.5f * a0;
            float z1 = (c + 1 == r ? 1.5f : 0.0f) - 0.5f * a1;
            __half p0, s0, p1, s1;
            uint32_t off = swz((uint32_t)(r * 128 + c * 2));
            split2(a0, p0, s0); split2(a1, p1, s1);
            *(uint32_t*)(smem + 4 * BUF + off) = packh(p0, p1);
            *(uint32_t*)(smem + 5 * BUF + off) = packh(s0, s1);
            split2(z0, p0, s0); split2(z1, p1, s1);
            *(uint32_t*)(smem + 2 * BUF + off) = packh(p0, p1);
            *(uint32_t*)(smem + 3 * BUF + off) = packh(s0, s1);
        }
    }

    // ---- Newton-Schulz chain (12 GEMMs) ----
    // Y = A @ Z   (dest 0,1 disjoint from 4,5 / 2,3)
    gemm_disjoint<0>(sbase, smem, 4*BUF, 5*BUF, 2*BUF, 3*BUF, 0*BUF, 1*BUF,
                     O, 0.f, wm, wn, lane);
#pragma unroll 1
    for (int it = 0; it < 3; ++it) {
        // T = 1.5I - 0.5 * Z@Y   (dest 4,5 disjoint)
        gemm_disjoint<1>(sbase, smem, 2*BUF, 3*BUF, 0*BUF, 1*BUF, 4*BUF, 5*BUF,
                         O, 0.f, wm, wn, lane);
        // Y' = Y @ T   (in-place on 0,1)
        gemm_inplace(sbase, smem, 0*BUF, 1*BUF, 4*BUF, 5*BUF, wm, wn, lane);
        // Z' = Z @ T   (== T@Z by commutativity; in-place on 2,3)
        gemm_inplace(sbase, smem, 2*BUF, 3*BUF, 4*BUF, 5*BUF, wm, wn, lane);
    }
    // T = 1.5I - 0.5 * Z@Y ; out = sqrt(normA) * (Y @ T)
    gemm_disjoint<1>(sbase, smem, 2*BUF, 3*BUF, 0*BUF, 1*BUF, 4*BUF, 5*BUF,
                     O, 0.f, wm, wn, lane);
    gemm_disjoint<2>(sbase, smem, 0*BUF, 1*BUF, 4*BUF, 5*BUF, 0, 0,
                     O, sq, wm, wn, lane);
}

extern "C" void kernel_launch(void* const* d_in, const int* in_sizes, int n_in,
                              void* d_out, int out_size)
{
    const float* x = (const float*)d_in[0];
    float* out = (float*)d_out;
    const int batches = in_sizes[0] / 4096;

    cudaFuncSetAttribute(isqrtm_hmma_kernel,
                         cudaFuncAttributeMaxDynamicSharedMemorySize, SMEM_TOTAL);
    isqrtm_hmma_kernel<<<batches, NT, SMEM_TOTAL>>>(x, out);
}

// round 13
// speedup vs baseline: 1.0617x; 1.0617x over previous
#include <cuda_runtime.h>
#include <cuda_fp16.h>
#include <math.h>
#include <stdint.h>

#define NT 128
#define BUF 8192                       // one 64x64 fp16 buffer: 64 rows x 128B
#define SMEM_TOTAL (6*BUF + 64)
// buffer roles: 0,1 = Y splits ; 2,3 = Z splits ; 4,5 = T/A splits

__device__ __forceinline__ uint32_t swz(uint32_t b) { return b ^ ((b >> 3) & 0x70); }

__device__ __forceinline__ uint32_t smem_u32(const void* p) {
    uint32_t a;
    asm("{ .reg .u64 t; cvta.to.shared.u64 t, %1; cvt.u32.u64 %0, t; }" : "=r"(a) : "l"(p));
    return a;
}

__device__ __forceinline__ void ldsm4(uint32_t* r, uint32_t addr) {
    asm volatile("ldmatrix.sync.aligned.m8n8.x4.shared.b16 {%0,%1,%2,%3}, [%4];"
                 : "=r"(r[0]), "=r"(r[1]), "=r"(r[2]), "=r"(r[3]) : "r"(addr));
}

__device__ __forceinline__ void mma16816(float* c, const uint32_t* a,
                                         uint32_t b0, uint32_t b1) {
    asm volatile("mma.sync.aligned.m16n8k16.row.col.f32.f16.f16.f32 "
                 "{%0,%1,%2,%3}, {%4,%5,%6,%7}, {%8,%9}, {%0,%1,%2,%3};"
                 : "+f"(c[0]), "+f"(c[1]), "+f"(c[2]), "+f"(c[3])
                 : "r"(a[0]), "r"(a[1]), "r"(a[2]), "r"(a[3]), "r"(b0), "r"(b1));
}

// fp32 -> 2-term fp16 split
__device__ __forceinline__ void split2(float v, __half& h1, __half& h2) {
    h1 = __float2half_rn(v);
    h2 = __float2half_rn(v - __half2float(h1));
}
__device__ __forceinline__ uint32_t packh(__half a, __half b) {
    __half2 t; t.x = a; t.y = b;
    return *reinterpret_cast<uint32_t*>(&t);
}

// ---- streamed MMA phase (round-7 layout): acc = (a1+a2)@(b1+b2), 3 products ----
__device__ __forceinline__ void mma_phase(uint32_t sbase,
                                          int a1, int a2, int b1, int b2,
                                          int wm, int wn, int lane,
                                          float acc[2][4][4])
{
#pragma unroll
    for (int mt = 0; mt < 2; ++mt)
#pragma unroll
        for (int j = 0; j < 4; ++j)
#pragma unroll
            for (int q = 0; q < 4; ++q) acc[mt][j][q] = 0.0f;

    const int arow = wm * 32 + (lane & 15);
    const int acol = (lane >> 4) * 16;
    const int bl = lane & 7;
    const int bg = lane >> 3;
    const uint32_t bcol = (uint32_t)((bg >> 1) * 32 + (bg & 1) * 16);

#pragma unroll
    for (int ktp = 0; ktp < 2; ++ktp) {
        uint32_t A1[2][2][4], A2[2][2][4];
#pragma unroll
        for (int mt = 0; mt < 2; ++mt)
#pragma unroll
            for (int ktl = 0; ktl < 2; ++ktl) {
                uint32_t rel = swz((uint32_t)((arow + mt * 16) * 128 +
                                              ktp * 64 + ktl * 32 + acol));
                ldsm4(A1[mt][ktl], sbase + a1 + rel);
                ldsm4(A2[mt][ktl], sbase + a2 + rel);
            }
#pragma unroll
        for (int j = 0; j < 4; ++j) {
            const uint32_t rowb = (uint32_t)((wn * 32 + j * 8 + bl) * 128);
            uint32_t rel = swz(rowb + ktp * 64 + bcol);
            uint32_t Bx[4], Cx[4];
            ldsm4(Bx, sbase + b1 + rel);   // regs 0,1 = kt_lo ; 2,3 = kt_hi
            ldsm4(Cx, sbase + b2 + rel);
#pragma unroll
            for (int ktl = 0; ktl < 2; ++ktl) {
#pragma unroll
                for (int mt = 0; mt < 2; ++mt) {
                    mma16816(acc[mt][j], A1[mt][ktl], Bx[2*ktl], Bx[2*ktl+1]);
                    mma16816(acc[mt][j], A1[mt][ktl], Cx[2*ktl], Cx[2*ktl+1]);
                    mma16816(acc[mt][j], A2[mt][ktl], Bx[2*ktl], Bx[2*ktl+1]);
                }
            }
        }
    }
}

// ---- epilogue: transform, split, store. No barriers inside. ----
// MODE 0: dst = D   MODE 1: dst = 1.5I - 0.5 D   MODE 2: gmem O = scale*D
template <int MODE>
__device__ __forceinline__ void epi_phase(char* smem, int d1, int d2,
                                          float* __restrict__ O, float scale,
                                          int wm, int wn, int lane,
                                          const float acc[2][4][4])
{
    const int gr = lane >> 2, qp = lane & 3;
#pragma unroll
    for (int mt = 0; mt < 2; ++mt)
#pragma unroll
    for (int j = 0; j < 4; ++j) {
        const int colb = wn * 32 + j * 8 + 2 * qp;
#pragma unroll
        for (int half = 0; half < 2; ++half) {
            const int row = wm * 32 + mt * 16 + gr + half * 8;
            float v0 = acc[mt][j][half * 2 + 0];
            float v1 = acc[mt][j][half * 2 + 1];
            if (MODE == 1) {
                v0 = (colb     == row ? 1.5f : 0.0f) - 0.5f * v0;
                v1 = (colb + 1 == row ? 1.5f : 0.0f) - 0.5f * v1;
            }
            if (MODE == 2) {
                *(float2*)(O + row * 64 + colb) = make_float2(v0 * scale, v1 * scale);
            } else {
                __half p0, q0, p1, q1;
                split2(v0, p0, q0);
                split2(v1, p1, q1);
                uint32_t off = swz((uint32_t)(row * 128 + colb * 2));
                *(uint32_t*)(smem + d1 + off) = packh(p0, p1);
                *(uint32_t*)(smem + d2 + off) = packh(q0, q1);
            }
        }
    }
}

// disjoint GEMM: dest intersects no source -> NO mid-barrier
template <int MODE>
__device__ __forceinline__ void gemm_disjoint(uint32_t sbase, char* smem,
                                              int a1, int a2, int b1, int b2,
                                              int d1, int d2,
                                              float* __restrict__ O, float scale,
                                              int wm, int wn, int lane)
{
    float acc[2][4][4];
    __syncthreads();            // previous epilogue writes visible
    mma_phase(sbase, a1, a2, b1, b2, wm, wn, lane, acc);
    epi_phase<MODE>(smem, d1, d2, O, scale, wm, wn, lane, acc);
}

// in-place GEMM (dest aliases a source): round-7 form with mid-barrier
template <int MODE>
__device__ __forceinline__ void gemm_inplace(uint32_t sbase, char* smem,
                                             int a1, int a2, int b1, int b2,
                                             int d1, int d2,
                                             float* __restrict__ O, float scale,
                                             int wm, int wn, int lane)
{
    float acc[2][4][4];
    __syncthreads();            // previous epilogue writes visible
    mma_phase(sbase, a1, a2, b1, b2, wm, wn, lane, acc);
    __syncthreads();            // all reads done before overwrite
    epi_phase<MODE>(smem, d1, d2, O, scale, wm, wn, lane, acc);
}

__global__ void __launch_bounds__(NT, 4)
isqrtm_hmma_kernel(const float* __restrict__ x, float* __restrict__ out)
{
    extern __shared__ char smem[];
    const uint32_t sbase = smem_u32(smem);
    float* red = (float*)(smem + 6 * BUF);

    const int tid = threadIdx.x;
    const int wid = tid >> 5, lane = tid & 31;
    const int wm = wid >> 1, wn = wid & 1;
    const int b = blockIdx.x;
    const float* X = x + (size_t)b * 4096;
    float* O = out + (size_t)b * 4096;

    // ---- trace(X) ----
    float tr = (tid < 64) ? __ldg(X + tid * 65) : 0.0f;
#pragma unroll
    for (int o = 16; o; o >>= 1) tr += __shfl_xor_sync(0xFFFFFFFFu, tr, o);
    if (lane == 0) red[wid] = tr;
    __syncthreads();
    const float normA = red[0] + red[1];
    const float inv = 1.0f / normA;
    const float sq  = sqrtf(normA);
    __syncthreads();

    // ---- prologue: A = X/normA -> bufs 4,5 ; Z = 1.5I - 0.5A -> bufs 2,3 ----
    {
        const int r  = tid >> 1;
        const int c0 = (tid & 1) * 32;
#pragma unroll
        for (int q = 0; q < 16; ++q) {
            const int c = c0 + 2 * q;
            float2 f = *(const float2*)(X + r * 64 + c);
            float a0 = f.x * inv, a1 = f.y * inv;
            float z0 = (c     == r ? 1.5f : 0.0f) - 0.5f * a0;
            float z1 = (c + 1 == r ? 1.5f : 0.0f) - 0.5f * a1;
            __half p0, s0, p1, s1;
            uint32_t off = swz((uint32_t)(r * 128 + c * 2));
            split2(a0, p0, s0); split2(a1, p1, s1);
            *(uint32_t*)(smem + 4 * BUF + off) = packh(p0, p1);
            *(uint32_t*)(smem + 5 * BUF + off) = packh(s0, s1);
            split2(z0, p0, s0); split2(z1, p1, s1);
            *(uint32_t*)(smem + 2 * BUF + off) = packh(p0, p1);
            *(uint32_t*)(smem + 3 * BUF + off) = packh(s0, s1);
        }
    }

    // ---- Newton-Schulz chain (12 GEMMs; 6 disjoint, 6 in-place) ----
    // Y = A @ Z   (dest 0,1 disjoint)
    gemm_disjoint<0>(sbase, smem, 4*BUF, 5*BUF, 2*BUF, 3*BUF, 0*BUF, 1*BUF,
                     O, 0.f, wm, wn, lane);
#pragma unroll 1
    for (int it = 0; it < 3; ++it) {
        // T = 1.5I - 0.5 * Z@Y   (dest 4,5 disjoint)
        gemm_disjoint<1>(sbase, smem, 2*BUF, 3*BUF, 0*BUF, 1*BUF, 4*BUF, 5*BUF,
                         O, 0.f, wm, wn, lane);
        // Y = Y @ T   (in-place on 0,1)
        gemm_inplace<0>(sbase, smem, 0*BUF, 1*BUF, 4*BUF, 5*BUF, 0*BUF, 1*BUF,
                        O, 0.f, wm, wn, lane);
        // Z = T @ Z   (in-place on 2,3)
        gemm_inplace<0>(sbase, smem, 4*BUF, 5*BUF, 2*BUF, 3*BUF, 2*BUF, 3*BUF,
                        O, 0.f, wm, wn, lane);
    }
    // T = 1.5I - 0.5 * Z@Y   (disjoint)
    gemm_disjoint<1>(sbase, smem, 2*BUF, 3*BUF, 0*BUF, 1*BUF, 4*BUF, 5*BUF,
                     O, 0.f, wm, wn, lane);
    // out = sqrt(normA) * (Y @ T)   (gmem dest, disjoint)
    gemm_disjoint<2>(sbase, smem, 0*BUF, 1*BUF, 4*BUF, 5*BUF, 0, 0,
                     O, sq, wm, wn, lane);
}

extern "C" void kernel_launch(void* const* d_in, const int* in_sizes, int n_in,
                              void* d_out, int out_size)
{
    const float* x = (const float*)d_in[0];
    float* out = (float*)d_out;
    const int batches = in_sizes[0] / 4096;

    cudaFuncSetAttribute(isqrtm_hmma_kernel,
                         cudaFuncAttributeMaxDynamicSharedMemorySize, SMEM_TOTAL);
    isqrtm_hmma_kernel<<<batches, NT, SMEM_TOTAL>>>(x, out);
}

// round 14
// speedup vs baseline: 1.0835x; 1.0205x over previous
#include <cuda_runtime.h>
#include <cuda_fp16.h>
#include <math.h>
#include <stdint.h>

#define NT 128
#define BUF 8192                       // one 64x64 fp16 buffer: 64 rows x 128B
#define SMEM_TOTAL (6*BUF + 64)
// buffer roles: 0,1 = Y splits ; 2,3 = Z splits ; 4,5 = T/A splits

__device__ __forceinline__ uint32_t swz(uint32_t b) { return b ^ ((b >> 3) & 0x70); }

__device__ __forceinline__ uint32_t smem_u32(const void* p) {
    uint32_t a;
    asm("{ .reg .u64 t; cvta.to.shared.u64 t, %1; cvt.u32.u64 %0, t; }" : "=r"(a) : "l"(p));
    return a;
}

__device__ __forceinline__ void ldsm4(uint32_t* r, uint32_t addr) {
    asm volatile("ldmatrix.sync.aligned.m8n8.x4.shared.b16 {%0,%1,%2,%3}, [%4];"
                 : "=r"(r[0]), "=r"(r[1]), "=r"(r[2]), "=r"(r[3]) : "r"(addr));
}

__device__ __forceinline__ void mma16816(float* c, const uint32_t* a,
                                         uint32_t b0, uint32_t b1) {
    asm volatile("mma.sync.aligned.m16n8k16.row.col.f32.f16.f16.f32 "
                 "{%0,%1,%2,%3}, {%4,%5,%6,%7}, {%8,%9}, {%0,%1,%2,%3};"
                 : "+f"(c[0]), "+f"(c[1]), "+f"(c[2]), "+f"(c[3])
                 : "r"(a[0]), "r"(a[1]), "r"(a[2]), "r"(a[3]), "r"(b0), "r"(b1));
}

// fp32 -> 2-term fp16 split
__device__ __forceinline__ void split2(float v, __half& h1, __half& h2) {
    h1 = __float2half_rn(v);
    h2 = __float2half_rn(v - __half2float(h1));
}
__device__ __forceinline__ uint32_t packh(__half a, __half b) {
    __half2 t; t.x = a; t.y = b;
    return *reinterpret_cast<uint32_t*>(&t);
}

// ---- streamed MMA phase: acc = (a1+a2)@(b1+b2) ----
// NP=3: products a1b1 + a1b2 + a2b1 (full precision)
// NP=2: products a1b1 + a1b2 (skips a2 loads entirely; ~2^-11 relative error)
template <int NP>
__device__ __forceinline__ void mma_phase(uint32_t sbase,
                                          int a1, int a2, int b1, int b2,
                                          int wm, int wn, int lane,
                                          float acc[2][4][4])
{
#pragma unroll
    for (int mt = 0; mt < 2; ++mt)
#pragma unroll
        for (int j = 0; j < 4; ++j)
#pragma unroll
            for (int q = 0; q < 4; ++q) acc[mt][j][q] = 0.0f;

    const int arow = wm * 32 + (lane & 15);
    const int acol = (lane >> 4) * 16;
    const int bl = lane & 7;
    const int bg = lane >> 3;
    const uint32_t bcol = (uint32_t)((bg >> 1) * 32 + (bg & 1) * 16);

#pragma unroll
    for (int ktp = 0; ktp < 2; ++ktp) {
        uint32_t A1[2][2][4], A2[2][2][4];
#pragma unroll
        for (int mt = 0; mt < 2; ++mt)
#pragma unroll
            for (int ktl = 0; ktl < 2; ++ktl) {
                uint32_t rel = swz((uint32_t)((arow + mt * 16) * 128 +
                                              ktp * 64 + ktl * 32 + acol));
                ldsm4(A1[mt][ktl], sbase + a1 + rel);
                if (NP == 3) ldsm4(A2[mt][ktl], sbase + a2 + rel);
            }
#pragma unroll
        for (int j = 0; j < 4; ++j) {
            const uint32_t rowb = (uint32_t)((wn * 32 + j * 8 + bl) * 128);
            uint32_t rel = swz(rowb + ktp * 64 + bcol);
            uint32_t Bx[4], Cx[4];
            ldsm4(Bx, sbase + b1 + rel);   // regs 0,1 = kt_lo ; 2,3 = kt_hi
            ldsm4(Cx, sbase + b2 + rel);
#pragma unroll
            for (int ktl = 0; ktl < 2; ++ktl) {
#pragma unroll
                for (int mt = 0; mt < 2; ++mt) {
                    mma16816(acc[mt][j], A1[mt][ktl], Bx[2*ktl], Bx[2*ktl+1]);
                    mma16816(acc[mt][j], A1[mt][ktl], Cx[2*ktl], Cx[2*ktl+1]);
                    if (NP == 3)
                        mma16816(acc[mt][j], A2[mt][ktl], Bx[2*ktl], Bx[2*ktl+1]);
                }
            }
        }
    }
}

// ---- epilogue: transform, split, store. No barriers inside. ----
// MODE 0: dst = D   MODE 1: dst = 1.5I - 0.5 D   MODE 2: gmem O = scale*D
template <int MODE>
__device__ __forceinline__ void epi_phase(char* smem, int d1, int d2,
                                          float* __restrict__ O, float scale,
                                          int wm, int wn, int lane,
                                          const float acc[2][4][4])
{
    const int gr = lane >> 2, qp = lane & 3;
#pragma unroll
    for (int mt = 0; mt < 2; ++mt)
#pragma unroll
    for (int j = 0; j < 4; ++j) {
        const int colb = wn * 32 + j * 8 + 2 * qp;
#pragma unroll
        for (int half = 0; half < 2; ++half) {
            const int row = wm * 32 + mt * 16 + gr + half * 8;
            float v0 = acc[mt][j][half * 2 + 0];
            float v1 = acc[mt][j][half * 2 + 1];
            if (MODE == 1) {
                v0 = (colb     == row ? 1.5f : 0.0f) - 0.5f * v0;
                v1 = (colb + 1 == row ? 1.5f : 0.0f) - 0.5f * v1;
            }
            if (MODE == 2) {
                *(float2*)(O + row * 64 + colb) = make_float2(v0 * scale, v1 * scale);
            } else {
                __half p0, q0, p1, q1;
                split2(v0, p0, q0);
                split2(v1, p1, q1);
                uint32_t off = swz((uint32_t)(row * 128 + colb * 2));
                *(uint32_t*)(smem + d1 + off) = packh(p0, p1);
                *(uint32_t*)(smem + d2 + off) = packh(q0, q1);
            }
        }
    }
}

// disjoint GEMM: dest intersects no source -> NO mid-barrier
template <int MODE, int NP>
__device__ __forceinline__ void gemm_disjoint(uint32_t sbase, char* smem,
                                              int a1, int a2, int b1, int b2,
                                              int d1, int d2,
                                              float* __restrict__ O, float scale,
                                              int wm, int wn, int lane)
{
    float acc[2][4][4];
    __syncthreads();            // previous epilogue writes visible
    mma_phase<NP>(sbase, a1, a2, b1, b2, wm, wn, lane, acc);
    epi_phase<MODE>(smem, d1, d2, O, scale, wm, wn, lane, acc);
}

// in-place GEMM (dest aliases a source): opening + mid barrier
template <int MODE>
__device__ __forceinline__ void gemm_inplace(uint32_t sbase, char* smem,
                                             int a1, int a2, int b1, int b2,
                                             int d1, int d2,
                                             float* __restrict__ O, float scale,
                                             int wm, int wn, int lane)
{
    float acc[2][4][4];
    __syncthreads();            // previous epilogue writes visible
    mma_phase<3>(sbase, a1, a2, b1, b2, wm, wn, lane, acc);
    __syncthreads();            // all reads done before overwrite
    epi_phase<MODE>(smem, d1, d2, O, scale, wm, wn, lane, acc);
}

// in-place GEMM with NO opening barrier: valid when the immediately preceding
// epilogue writes buffers disjoint from this GEMM's sources (writes to the
// sources were already ordered by an earlier barrier). The mid-barrier still
// guards this GEMM's own read-before-overwrite hazard, including stragglers
// (a late warp reaches its reads in program order; early warps' writes wait
// at the mid-barrier).
template <int MODE>
__device__ __forceinline__ void gemm_inplace_noopen(uint32_t sbase, char* smem,
                                                    int a1, int a2, int b1, int b2,
                                                    int d1, int d2,
                                                    float* __restrict__ O, float scale,
                                                    int wm, int wn, int lane)
{
    float acc[2][4][4];
    mma_phase<3>(sbase, a1, a2, b1, b2, wm, wn, lane, acc);
    __syncthreads();            // all reads done before overwrite
    epi_phase<MODE>(smem, d1, d2, O, scale, wm, wn, lane, acc);
}

__global__ void __launch_bounds__(NT, 4)
isqrtm_hmma_kernel(const float* __restrict__ x, float* __restrict__ out)
{
    extern __shared__ char smem[];
    const uint32_t sbase = smem_u32(smem);
    float* red = (float*)(smem + 6 * BUF);

    const int tid = threadIdx.x;
    const int wid = tid >> 5, lane = tid & 31;
    const int wm = wid >> 1, wn = wid & 1;
    const int b = blockIdx.x;
    const float* X = x + (size_t)b * 4096;
    float* O = out + (size_t)b * 4096;

    // ---- trace(X) ----
    float tr = (tid < 64) ? __ldg(X + tid * 65) : 0.0f;
#pragma unroll
    for (int o = 16; o; o >>= 1) tr += __shfl_xor_sync(0xFFFFFFFFu, tr, o);
    if (lane == 0) red[wid] = tr;
    __syncthreads();
    const float normA = red[0] + red[1];
    const float inv = 1.0f / normA;
    const float sq  = sqrtf(normA);
    __syncthreads();

    // ---- prologue: A = X/normA -> bufs 4,5 ; Z = 1.5I - 0.5A -> bufs 2,3 ----
    {
        const int r  = tid >> 1;
        const int c0 = (tid & 1) * 32;
#pragma unroll
        for (int q = 0; q < 16; ++q) {
            const int c = c0 + 2 * q;
            float2 f = *(const float2*)(X + r * 64 + c);
            float a0 = f.x * inv, a1 = f.y * inv;
            float z0 = (c     == r ? 1.5f : 0.0f) - 0.5f * a0;
            float z1 = (c + 1 == r ? 1.5f : 0.0f) - 0.5f * a1;
            __half p0, s0, p1, s1;
            uint32_t off = swz((uint32_t)(r * 128 + c * 2));
            split2(a0, p0, s0); split2(a1, p1, s1);
            *(uint32_t*)(smem + 4 * BUF + off) = packh(p0, p1);
            *(uint32_t*)(smem + 5 * BUF + off) = packh(s0, s1);
            split2(z0, p0, s0); split2(z1, p1, s1);
            *(uint32_t*)(smem + 2 * BUF + off) = packh(p0, p1);
            *(uint32_t*)(smem + 3 * BUF + off) = packh(s0, s1);
        }
    }

    // ---- Newton-Schulz chain (12 GEMMs; 15 barriers) ----
    // Y = A @ Z   (dest 0,1 disjoint)
    gemm_disjoint<0,3>(sbase, smem, 4*BUF, 5*BUF, 2*BUF, 3*BUF, 0*BUF, 1*BUF,
                       O, 0.f, wm, wn, lane);
#pragma unroll 1
    for (int it = 0; it < 3; ++it) {
        // T = 1.5I - 0.5 * Z@Y   (dest 4,5 disjoint)
        gemm_disjoint<1,3>(sbase, smem, 2*BUF, 3*BUF, 0*BUF, 1*BUF, 4*BUF, 5*BUF,
                           O, 0.f, wm, wn, lane);
        // Y = Y @ T   (in-place on 0,1; preceding epi wrote 4,5 -> opening bar)
        gemm_inplace<0>(sbase, smem, 0*BUF, 1*BUF, 4*BUF, 5*BUF, 0*BUF, 1*BUF,
                        O, 0.f, wm, wn, lane);
        // Z = T @ Z   (in-place on 2,3; preceding epi wrote only 0,1 -> NO opening bar)
        gemm_inplace_noopen<0>(sbase, smem, 4*BUF, 5*BUF, 2*BUF, 3*BUF, 2*BUF, 3*BUF,
                               O, 0.f, wm, wn, lane);
    }
    // T = 1.5I - 0.5 * Z@Y   (disjoint; preceding epi wrote 2,3 which T reads -> bar kept)
    gemm_disjoint<1,3>(sbase, smem, 2*BUF, 3*BUF, 0*BUF, 1*BUF, 4*BUF, 5*BUF,
                       O, 0.f, wm, wn, lane);
    // out = sqrt(normA) * (Y @ T)   (gmem dest; 2-product: drop y2*t1 cross term)
    gemm_disjoint<2,2>(sbase, smem, 0*BUF, 1*BUF, 4*BUF, 5*BUF, 0, 0,
                       O, sq, wm, wn, lane);
}

extern "C" void kernel_launch(void* const* d_in, const int* in_sizes, int n_in,
                              void* d_out, int out_size)
{
    const float* x = (const float*)d_in[0];
    float* out = (float*)d_out;
    const int batches = in_sizes[0] / 4096;

    cudaFuncSetAttribute(isqrtm_hmma_kernel,
                         cudaFuncAttributeMaxDynamicSharedMemorySize, SMEM_TOTAL);
    isqrtm_hmma_kernel<<<batches, NT, SMEM_TOTAL>>>(x, out);
}

// round 15
// speedup vs baseline: 1.1577x; 1.0685x over previous
#include <cuda_runtime.h>
#include <cuda_fp16.h>
#include <math.h>
#include <stdint.h>

#define NT 128
#define BUF 8192                       // one 64x64 fp16 buffer: 64 rows x 128B
#define SMEM_TOTAL (6*BUF + 64)
// buffer roles: 0,1 = Y splits ; 2,3 = Z splits ; 4,5 = T/A splits

__device__ __forceinline__ uint32_t swz(uint32_t b) { return b ^ ((b >> 3) & 0x70); }

__device__ __forceinline__ uint32_t smem_u32(const void* p) {
    uint32_t a;
    asm("{ .reg .u64 t; cvta.to.shared.u64 t, %1; cvt.u32.u64 %0, t; }" : "=r"(a) : "l"(p));
    return a;
}

__device__ __forceinline__ void ldsm4(uint32_t* r, uint32_t addr) {
    asm volatile("ldmatrix.sync.aligned.m8n8.x4.shared.b16 {%0,%1,%2,%3}, [%4];"
                 : "=r"(r[0]), "=r"(r[1]), "=r"(r[2]), "=r"(r[3]) : "r"(addr));
}

__device__ __forceinline__ void mma16816(float* c, const uint32_t* a,
                                         uint32_t b0, uint32_t b1) {
    asm volatile("mma.sync.aligned.m16n8k16.row.col.f32.f16.f16.f32 "
                 "{%0,%1,%2,%3}, {%4,%5,%6,%7}, {%8,%9}, {%0,%1,%2,%3};"
                 : "+f"(c[0]), "+f"(c[1]), "+f"(c[2]), "+f"(c[3])
                 : "r"(a[0]), "r"(a[1]), "r"(a[2]), "r"(a[3]), "r"(b0), "r"(b1));
}

// fp32 -> 2-term fp16 split
__device__ __forceinline__ void split2(float v, __half& h1, __half& h2) {
    h1 = __float2half_rn(v);
    h2 = __float2half_rn(v - __half2float(h1));
}
__device__ __forceinline__ uint32_t packh(__half a, __half b) {
    __half2 t; t.x = a; t.y = b;
    return *reinterpret_cast<uint32_t*>(&t);
}

// ---- streamed MMA phase: acc = (a1+a2)@(b1+b2) ----
// NP=3: products a1b1 + a1b2 + a2b1 (full precision)
// NP=2: products a1b1 + a1b2 (skips a2 loads entirely; ~2^-11 term dropped)
template <int NP>
__device__ __forceinline__ void mma_phase(uint32_t sbase,
                                          int a1, int a2, int b1, int b2,
                                          int wm, int wn, int lane,
                                          float acc[2][4][4])
{
#pragma unroll
    for (int mt = 0; mt < 2; ++mt)
#pragma unroll
        for (int j = 0; j < 4; ++j)
#pragma unroll
            for (int q = 0; q < 4; ++q) acc[mt][j][q] = 0.0f;

    const int arow = wm * 32 + (lane & 15);
    const int acol = (lane >> 4) * 16;
    const int bl = lane & 7;
    const int bg = lane >> 3;
    const uint32_t bcol = (uint32_t)((bg >> 1) * 32 + (bg & 1) * 16);

#pragma unroll
    for (int ktp = 0; ktp < 2; ++ktp) {
        uint32_t A1[2][2][4], A2[2][2][4];
#pragma unroll
        for (int mt = 0; mt < 2; ++mt)
#pragma unroll
            for (int ktl = 0; ktl < 2; ++ktl) {
                uint32_t rel = swz((uint32_t)((arow + mt * 16) * 128 +
                                              ktp * 64 + ktl * 32 + acol));
                ldsm4(A1[mt][ktl], sbase + a1 + rel);
                if (NP == 3) ldsm4(A2[mt][ktl], sbase + a2 + rel);
            }
#pragma unroll
        for (int j = 0; j < 4; ++j) {
            const uint32_t rowb = (uint32_t)((wn * 32 + j * 8 + bl) * 128);
            uint32_t rel = swz(rowb + ktp * 64 + bcol);
            uint32_t Bx[4], Cx[4];
            ldsm4(Bx, sbase + b1 + rel);   // regs 0,1 = kt_lo ; 2,3 = kt_hi
            ldsm4(Cx, sbase + b2 + rel);
#pragma unroll
            for (int ktl = 0; ktl < 2; ++ktl) {
#pragma unroll
                for (int mt = 0; mt < 2; ++mt) {
                    mma16816(acc[mt][j], A1[mt][ktl], Bx[2*ktl], Bx[2*ktl+1]);
                    mma16816(acc[mt][j], A1[mt][ktl], Cx[2*ktl], Cx[2*ktl+1]);
                    if (NP == 3)
                        mma16816(acc[mt][j], A2[mt][ktl], Bx[2*ktl], Bx[2*ktl+1]);
                }
            }
        }
    }
}

// ---- epilogue: transform, split, store. No barriers inside. ----
// MODE 0: dst = D   MODE 1: dst = 1.5I - 0.5 D   MODE 2: gmem O = scale*D
template <int MODE>
__device__ __forceinline__ void epi_phase(char* smem, int d1, int d2,
                                          float* __restrict__ O, float scale,
                                          int wm, int wn, int lane,
                                          const float acc[2][4][4])
{
    const int gr = lane >> 2, qp = lane & 3;
#pragma unroll
    for (int mt = 0; mt < 2; ++mt)
#pragma unroll
    for (int j = 0; j < 4; ++j) {
        const int colb = wn * 32 + j * 8 + 2 * qp;
#pragma unroll
        for (int half = 0; half < 2; ++half) {
            const int row = wm * 32 + mt * 16 + gr + half * 8;
            float v0 = acc[mt][j][half * 2 + 0];
            float v1 = acc[mt][j][half * 2 + 1];
            if (MODE == 1) {
                v0 = (colb     == row ? 1.5f : 0.0f) - 0.5f * v0;
                v1 = (colb + 1 == row ? 1.5f : 0.0f) - 0.5f * v1;
            }
            if (MODE == 2) {
                *(float2*)(O + row * 64 + colb) = make_float2(v0 * scale, v1 * scale);
            } else {
                __half p0, q0, p1, q1;
                split2(v0, p0, q0);
                split2(v1, p1, q1);
                uint32_t off = swz((uint32_t)(row * 128 + colb * 2));
                *(uint32_t*)(smem + d1 + off) = packh(p0, p1);
                *(uint32_t*)(smem + d2 + off) = packh(q0, q1);
            }
        }
    }
}

// disjoint GEMM: dest intersects no source -> NO mid-barrier
template <int MODE, int NP>
__device__ __forceinline__ void gemm_disjoint(uint32_t sbase, char* smem,
                                              int a1, int a2, int b1, int b2,
                                              int d1, int d2,
                                              float* __restrict__ O, float scale,
                                              int wm, int wn, int lane)
{
    float acc[2][4][4];
    __syncthreads();            // previous epilogue writes visible
    mma_phase<NP>(sbase, a1, a2, b1, b2, wm, wn, lane, acc);
    epi_phase<MODE>(smem, d1, d2, O, scale, wm, wn, lane, acc);
}

// in-place GEMM (dest aliases a source): opening + mid barrier
template <int MODE>
__device__ __forceinline__ void gemm_inplace(uint32_t sbase, char* smem,
                                             int a1, int a2, int b1, int b2,
                                             int d1, int d2,
                                             float* __restrict__ O, float scale,
                                             int wm, int wn, int lane)
{
    float acc[2][4][4];
    __syncthreads();            // previous epilogue writes visible
    mma_phase<3>(sbase, a1, a2, b1, b2, wm, wn, lane, acc);
    __syncthreads();            // all reads done before overwrite
    epi_phase<MODE>(smem, d1, d2, O, scale, wm, wn, lane, acc);
}

// in-place GEMM with NO opening barrier: valid when the immediately preceding
// epilogue wrote buffers disjoint from this GEMM's sources (source writes were
// ordered by an earlier barrier). The mid-barrier still guards this GEMM's own
// read-before-overwrite hazard.
template <int MODE>
__device__ __forceinline__ void gemm_inplace_noopen(uint32_t sbase, char* smem,
                                                    int a1, int a2, int b1, int b2,
                                                    int d1, int d2,
                                                    float* __restrict__ O, float scale,
                                                    int wm, int wn, int lane)
{
    float acc[2][4][4];
    mma_phase<3>(sbase, a1, a2, b1, b2, wm, wn, lane, acc);
    __syncthreads();            // all reads done before overwrite
    epi_phase<MODE>(smem, d1, d2, O, scale, wm, wn, lane, acc);
}

__global__ void __launch_bounds__(NT, 4)
isqrtm_hmma_kernel(const float* __restrict__ x, float* __restrict__ out)
{
    extern __shared__ char smem[];
    const uint32_t sbase = smem_u32(smem);
    float* red = (float*)(smem + 6 * BUF);

    const int tid = threadIdx.x;
    const int wid = tid >> 5, lane = tid & 31;
    const int wm = wid >> 1, wn = wid & 1;
    const int b = blockIdx.x;
    const float* X = x + (size_t)b * 4096;
    float* O = out + (size_t)b * 4096;

    // ---- trace(X) ----
    float tr = (tid < 64) ? __ldg(X + tid * 65) : 0.0f;
#pragma unroll
    for (int o = 16; o; o >>= 1) tr += __shfl_xor_sync(0xFFFFFFFFu, tr, o);
    if (lane == 0) red[wid] = tr;
    __syncthreads();
    const float normA = red[0] + red[1];
    const float inv = 1.0f / normA;
    const float sq  = sqrtf(normA);
    __syncthreads();

    // ---- prologue: A = X/normA -> bufs 4,5 ; Z = 1.5I - 0.5A -> bufs 2,3 ----
    {
        const int r  = tid >> 1;
        const int c0 = (tid & 1) * 32;
#pragma unroll
        for (int q = 0; q < 16; ++q) {
            const int c = c0 + 2 * q;
            float2 f = *(const float2*)(X + r * 64 + c);
            float a0 = f.x * inv, a1 = f.y * inv;
            float z0 = (c     == r ? 1.5f : 0.0f) - 0.5f * a0;
            float z1 = (c + 1 == r ? 1.5f : 0.0f) - 0.5f * a1;
            __half p0, s0, p1, s1;
            uint32_t off = swz((uint32_t)(r * 128 + c * 2));
            split2(a0, p0, s0); split2(a1, p1, s1);
            *(uint32_t*)(smem + 4 * BUF + off) = packh(p0, p1);
            *(uint32_t*)(smem + 5 * BUF + off) = packh(s0, s1);
            split2(z0, p0, s0); split2(z1, p1, s1);
            *(uint32_t*)(smem + 2 * BUF + off) = packh(p0, p1);
            *(uint32_t*)(smem + 3 * BUF + off) = packh(s0, s1);
        }
    }

    // ---- Newton-Schulz chain (12 GEMMs; NP=2 on late T-steps + final out) ----
    // Y = A @ Z   (full precision)
    gemm_disjoint<0,3>(sbase, smem, 4*BUF, 5*BUF, 2*BUF, 3*BUF, 0*BUF, 1*BUF,
                       O, 0.f, wm, wn, lane);

    // --- it = 0 (earliest: full precision everywhere) ---
    gemm_disjoint<1,3>(sbase, smem, 2*BUF, 3*BUF, 0*BUF, 1*BUF, 4*BUF, 5*BUF,
                       O, 0.f, wm, wn, lane);
    gemm_inplace<0>(sbase, smem, 0*BUF, 1*BUF, 4*BUF, 5*BUF, 0*BUF, 1*BUF,
                    O, 0.f, wm, wn, lane);
    gemm_inplace_noopen<0>(sbase, smem, 4*BUF, 5*BUF, 2*BUF, 3*BUF, 2*BUF, 3*BUF,
                           O, 0.f, wm, wn, lane);

    // --- it = 1 (T-step at NP=2: error enters T halved) ---
    gemm_disjoint<1,2>(sbase, smem, 2*BUF, 3*BUF, 0*BUF, 1*BUF, 4*BUF, 5*BUF,
                       O, 0.f, wm, wn, lane);
    gemm_inplace<0>(sbase, smem, 0*BUF, 1*BUF, 4*BUF, 5*BUF, 0*BUF, 1*BUF,
                    O, 0.f, wm, wn, lane);
    gemm_inplace_noopen<0>(sbase, smem, 4*BUF, 5*BUF, 2*BUF, 3*BUF, 2*BUF, 3*BUF,
                           O, 0.f, wm, wn, lane);

    // --- it = 2 (T-step at NP=2) ---
    gemm_disjoint<1,2>(sbase, smem, 2*BUF, 3*BUF, 0*BUF, 1*BUF, 4*BUF, 5*BUF,
                       O, 0.f, wm, wn, lane);
    gemm_inplace<0>(sbase, smem, 0*BUF, 1*BUF, 4*BUF, 5*BUF, 0*BUF, 1*BUF,
                    O, 0.f, wm, wn, lane);
    gemm_inplace_noopen<0>(sbase, smem, 4*BUF, 5*BUF, 2*BUF, 3*BUF, 2*BUF, 3*BUF,
                           O, 0.f, wm, wn, lane);

    // final T = 1.5I - 0.5 * Z@Y   (NP=2)
    gemm_disjoint<1,2>(sbase, smem, 2*BUF, 3*BUF, 0*BUF, 1*BUF, 4*BUF, 5*BUF,
                       O, 0.f, wm, wn, lane);
    // out = sqrt(normA) * (Y @ T)   (NP=2, gmem dest)
    gemm_disjoint<2,2>(sbase, smem, 0*BUF, 1*BUF, 4*BUF, 5*BUF, 0, 0,
                       O, sq, wm, wn, lane);
}

extern "C" void kernel_launch(void* const* d_in, const int* in_sizes, int n_in,
                              void* d_out, int out_size)
{
    const float* x = (const float*)d_in[0];
    float* out = (float*)d_out;
    const int batches = in_sizes[0] / 4096;

    cudaFuncSetAttribute(isqrtm_hmma_kernel,
                         cudaFuncAttributeMaxDynamicSharedMemorySize, SMEM_TOTAL);
    isqrtm_hmma_kernel<<<batches, NT, SMEM_TOTAL>>>(x, out);
}

// round 16
// speedup vs baseline: 1.2548x; 1.0839x over previous
#include <cuda_runtime.h>
#include <cuda_fp16.h>
#include <math.h>
#include <stdint.h>

#define NT 128
#define BUF 8192                       // one 64x64 fp16 buffer: 64 rows x 128B
#define SMEM_TOTAL (6*BUF + 64)
// buffer roles: 0,1 = Y splits ; 2,3 = Z splits ; 4,5 = T/A splits

__device__ __forceinline__ uint32_t swz(uint32_t b) { return b ^ ((b >> 3) & 0x70); }

__device__ __forceinline__ uint32_t smem_u32(const void* p) {
    uint32_t a;
    asm("{ .reg .u64 t; cvta.to.shared.u64 t, %1; cvt.u32.u64 %0, t; }" : "=r"(a) : "l"(p));
    return a;
}

__device__ __forceinline__ void ldsm4(uint32_t* r, uint32_t addr) {
    asm volatile("ldmatrix.sync.aligned.m8n8.x4.shared.b16 {%0,%1,%2,%3}, [%4];"
                 : "=r"(r[0]), "=r"(r[1]), "=r"(r[2]), "=r"(r[3]) : "r"(addr));
}

__device__ __forceinline__ void mma16816(float* c, const uint32_t* a,
                                         uint32_t b0, uint32_t b1) {
    asm volatile("mma.sync.aligned.m16n8k16.row.col.f32.f16.f16.f32 "
                 "{%0,%1,%2,%3}, {%4,%5,%6,%7}, {%8,%9}, {%0,%1,%2,%3};"
                 : "+f"(c[0]), "+f"(c[1]), "+f"(c[2]), "+f"(c[3])
                 : "r"(a[0]), "r"(a[1]), "r"(a[2]), "r"(a[3]), "r"(b0), "r"(b1));
}

// fp32 -> 2-term fp16 split
__device__ __forceinline__ void split2(float v, __half& h1, __half& h2) {
    h1 = __float2half_rn(v);
    h2 = __float2half_rn(v - __half2float(h1));
}
__device__ __forceinline__ uint32_t packh(__half a, __half b) {
    __half2 t; t.x = a; t.y = b;
    return *reinterpret_cast<uint32_t*>(&t);
}

// ---- streamed MMA phase: acc = (a1+a2)@(b1+b2) ----
// NP=3: products a1b1 + a1b2 + a2b1 (full precision)
// NP=2: products a1b1 + a1b2 (skips a2 loads entirely; ~2^-11 term dropped)
template <int NP>
__device__ __forceinline__ void mma_phase(uint32_t sbase,
                                          int a1, int a2, int b1, int b2,
                                          int wm, int wn, int lane,
                                          float acc[2][4][4])
{
#pragma unroll
    for (int mt = 0; mt < 2; ++mt)
#pragma unroll
        for (int j = 0; j < 4; ++j)
#pragma unroll
            for (int q = 0; q < 4; ++q) acc[mt][j][q] = 0.0f;

    const int arow = wm * 32 + (lane & 15);
    const int acol = (lane >> 4) * 16;
    const int bl = lane & 7;
    const int bg = lane >> 3;
    const uint32_t bcol = (uint32_t)((bg >> 1) * 32 + (bg & 1) * 16);

#pragma unroll
    for (int ktp = 0; ktp < 2; ++ktp) {
        uint32_t A1[2][2][4], A2[2][2][4];
#pragma unroll
        for (int mt = 0; mt < 2; ++mt)
#pragma unroll
            for (int ktl = 0; ktl < 2; ++ktl) {
                uint32_t rel = swz((uint32_t)((arow + mt * 16) * 128 +
                                              ktp * 64 + ktl * 32 + acol));
                ldsm4(A1[mt][ktl], sbase + a1 + rel);
                if (NP == 3) ldsm4(A2[mt][ktl], sbase + a2 + rel);
            }
#pragma unroll
        for (int j = 0; j < 4; ++j) {
            const uint32_t rowb = (uint32_t)((wn * 32 + j * 8 + bl) * 128);
            uint32_t rel = swz(rowb + ktp * 64 + bcol);
            uint32_t Bx[4], Cx[4];
            ldsm4(Bx, sbase + b1 + rel);   // regs 0,1 = kt_lo ; 2,3 = kt_hi
            ldsm4(Cx, sbase + b2 + rel);
#pragma unroll
            for (int ktl = 0; ktl < 2; ++ktl) {
#pragma unroll
                for (int mt = 0; mt < 2; ++mt) {
                    mma16816(acc[mt][j], A1[mt][ktl], Bx[2*ktl], Bx[2*ktl+1]);
                    mma16816(acc[mt][j], A1[mt][ktl], Cx[2*ktl], Cx[2*ktl+1]);
                    if (NP == 3)
                        mma16816(acc[mt][j], A2[mt][ktl], Bx[2*ktl], Bx[2*ktl+1]);
                }
            }
        }
    }
}

// ---- epilogue: transform, split, store. No barriers inside. ----
// MODE 0: dst = D   MODE 1: dst = 1.5I - 0.5 D   MODE 2: gmem O = scale*D
template <int MODE>
__device__ __forceinline__ void epi_phase(char* smem, int d1, int d2,
                                          float* __restrict__ O, float scale,
                                          int wm, int wn, int lane,
                                          const float acc[2][4][4])
{
    const int gr = lane >> 2, qp = lane & 3;
#pragma unroll
    for (int mt = 0; mt < 2; ++mt)
#pragma unroll
    for (int j = 0; j < 4; ++j) {
        const int colb = wn * 32 + j * 8 + 2 * qp;
#pragma unroll
        for (int half = 0; half < 2; ++half) {
            const int row = wm * 32 + mt * 16 + gr + half * 8;
            float v0 = acc[mt][j][half * 2 + 0];
            float v1 = acc[mt][j][half * 2 + 1];
            if (MODE == 1) {
                v0 = (colb     == row ? 1.5f : 0.0f) - 0.5f * v0;
                v1 = (colb + 1 == row ? 1.5f : 0.0f) - 0.5f * v1;
            }
            if (MODE == 2) {
                *(float2*)(O + row * 64 + colb) = make_float2(v0 * scale, v1 * scale);
            } else {
                __half p0, q0, p1, q1;
                split2(v0, p0, q0);
                split2(v1, p1, q1);
                uint32_t off = swz((uint32_t)(row * 128 + colb * 2));
                *(uint32_t*)(smem + d1 + off) = packh(p0, p1);
                *(uint32_t*)(smem + d2 + off) = packh(q0, q1);
            }
        }
    }
}

// disjoint GEMM: dest intersects no source -> NO mid-barrier
template <int MODE, int NP>
__device__ __forceinline__ void gemm_disjoint(uint32_t sbase, char* smem,
                                              int a1, int a2, int b1, int b2,
                                              int d1, int d2,
                                              float* __restrict__ O, float scale,
                                              int wm, int wn, int lane)
{
    float acc[2][4][4];
    __syncthreads();            // previous epilogue writes visible
    mma_phase<NP>(sbase, a1, a2, b1, b2, wm, wn, lane, acc);
    epi_phase<MODE>(smem, d1, d2, O, scale, wm, wn, lane, acc);
}

// in-place GEMM (dest aliases a source): opening + mid barrier
template <int MODE, int NP>
__device__ __forceinline__ void gemm_inplace(uint32_t sbase, char* smem,
                                             int a1, int a2, int b1, int b2,
                                             int d1, int d2,
                                             float* __restrict__ O, float scale,
                                             int wm, int wn, int lane)
{
    float acc[2][4][4];
    __syncthreads();            // previous epilogue writes visible
    mma_phase<NP>(sbase, a1, a2, b1, b2, wm, wn, lane, acc);
    __syncthreads();            // all reads done before overwrite
    epi_phase<MODE>(smem, d1, d2, O, scale, wm, wn, lane, acc);
}

// in-place GEMM with NO opening barrier: valid when the immediately preceding
// epilogue wrote buffers disjoint from this GEMM's sources (source writes were
// ordered by an earlier barrier). The mid-barrier still guards this GEMM's own
// read-before-overwrite hazard.
template <int MODE, int NP>
__device__ __forceinline__ void gemm_inplace_noopen(uint32_t sbase, char* smem,
                                                    int a1, int a2, int b1, int b2,
                                                    int d1, int d2,
                                                    float* __restrict__ O, float scale,
                                                    int wm, int wn, int lane)
{
    float acc[2][4][4];
    mma_phase<NP>(sbase, a1, a2, b1, b2, wm, wn, lane, acc);
    __syncthreads();            // all reads done before overwrite
    epi_phase<MODE>(smem, d1, d2, O, scale, wm, wn, lane, acc);
}

__global__ void __launch_bounds__(NT, 4)
isqrtm_hmma_kernel(const float* __restrict__ x, float* __restrict__ out)
{
    extern __shared__ char smem[];
    const uint32_t sbase = smem_u32(smem);
    float* red = (float*)(smem + 6 * BUF);

    const int tid = threadIdx.x;
    const int wid = tid >> 5, lane = tid & 31;
    const int wm = wid >> 1, wn = wid & 1;
    const int b = blockIdx.x;
    const float* X = x + (size_t)b * 4096;
    float* O = out + (size_t)b * 4096;

    // ---- trace(X) ----
    float tr = (tid < 64) ? __ldg(X + tid * 65) : 0.0f;
#pragma unroll
    for (int o = 16; o; o >>= 1) tr += __shfl_xor_sync(0xFFFFFFFFu, tr, o);
    if (lane == 0) red[wid] = tr;
    __syncthreads();
    const float normA = red[0] + red[1];
    const float inv = 1.0f / normA;
    const float sq  = sqrtf(normA);
    __syncthreads();

    // ---- prologue: A = X/normA -> bufs 4,5 ; Z = 1.5I - 0.5A -> bufs 2,3 ----
    {
        const int r  = tid >> 1;
        const int c0 = (tid & 1) * 32;
#pragma unroll
        for (int q = 0; q < 16; ++q) {
            const int c = c0 + 2 * q;
            float2 f = *(const float2*)(X + r * 64 + c);
            float a0 = f.x * inv, a1 = f.y * inv;
            float z0 = (c     == r ? 1.5f : 0.0f) - 0.5f * a0;
            float z1 = (c + 1 == r ? 1.5f : 0.0f) - 0.5f * a1;
            __half p0, s0, p1, s1;
            uint32_t off = swz((uint32_t)(r * 128 + c * 2));
            split2(a0, p0, s0); split2(a1, p1, s1);
            *(uint32_t*)(smem + 4 * BUF + off) = packh(p0, p1);
            *(uint32_t*)(smem + 5 * BUF + off) = packh(s0, s1);
            split2(z0, p0, s0); split2(z1, p1, s1);
            *(uint32_t*)(smem + 2 * BUF + off) = packh(p0, p1);
            *(uint32_t*)(smem + 3 * BUF + off) = packh(s0, s1);
        }
    }

    // ---- Newton-Schulz chain: NP=3 anchors on the 3 earliest GEMMs,
    //      NP=2 everywhere else (mid-chain errors are damped; measured) ----
    // Y = A @ Z   (full precision)
    gemm_disjoint<0,3>(sbase, smem, 4*BUF, 5*BUF, 2*BUF, 3*BUF, 0*BUF, 1*BUF,
                       O, 0.f, wm, wn, lane);

    // --- it = 0: T at NP=2 (10 GEMMs of damping runway), Y/Z anchors NP=3 ---
    gemm_disjoint<1,2>(sbase, smem, 2*BUF, 3*BUF, 0*BUF, 1*BUF, 4*BUF, 5*BUF,
                       O, 0.f, wm, wn, lane);
    gemm_inplace<0,3>(sbase, smem, 0*BUF, 1*BUF, 4*BUF, 5*BUF, 0*BUF, 1*BUF,
                      O, 0.f, wm, wn, lane);
    gemm_inplace_noopen<0,3>(sbase, smem, 4*BUF, 5*BUF, 2*BUF, 3*BUF, 2*BUF, 3*BUF,
                             O, 0.f, wm, wn, lane);

    // --- it = 1: all NP=2 ---
    gemm_disjoint<1,2>(sbase, smem, 2*BUF, 3*BUF, 0*BUF, 1*BUF, 4*BUF, 5*BUF,
                       O, 0.f, wm, wn, lane);
    gemm_inplace<0,2>(sbase, smem, 0*BUF, 1*BUF, 4*BUF, 5*BUF, 0*BUF, 1*BUF,
                      O, 0.f, wm, wn, lane);
    gemm_inplace_noopen<0,2>(sbase, smem, 4*BUF, 5*BUF, 2*BUF, 3*BUF, 2*BUF, 3*BUF,
                             O, 0.f, wm, wn, lane);

    // --- it = 2: all NP=2 ---
    gemm_disjoint<1,2>(sbase, smem, 2*BUF, 3*BUF, 0*BUF, 1*BUF, 4*BUF, 5*BUF,
                       O, 0.f, wm, wn, lane);
    gemm_inplace<0,2>(sbase, smem, 0*BUF, 1*BUF, 4*BUF, 5*BUF, 0*BUF, 1*BUF,
                      O, 0.f, wm, wn, lane);
    gemm_inplace_noopen<0,2>(sbase, smem, 4*BUF, 5*BUF, 2*BUF, 3*BUF, 2*BUF, 3*BUF,
                             O, 0.f, wm, wn, lane);

    // final T = 1.5I - 0.5 * Z@Y   (NP=2)
    gemm_disjoint<1,2>(sbase, smem, 2*BUF, 3*BUF, 0*BUF, 1*BUF, 4*BUF, 5*BUF,
                       O, 0.f, wm, wn, lane);
    // out = sqrt(normA) * (Y @ T)   (NP=2, gmem dest)
    gemm_disjoint<2,2>(sbase, smem, 0*BUF, 1*BUF, 4*BUF, 5*BUF, 0, 0,
                       O, sq, wm, wn, lane);
}

extern "C" void kernel_launch(void* const* d_in, const int* in_sizes, int n_in,
                              void* d_out, int out_size)
{
    const float* x = (const float*)d_in[0];
    float* out = (float*)d_out;
    const int batches = in_sizes[0] / 4096;

    cudaFuncSetAttribute(isqrtm_hmma_kernel,
                         cudaFuncAttributeMaxDynamicSharedMemorySize, SMEM_TOTAL);
    isqrtm_hmma_kernel<<<batches, NT, SMEM_TOTAL>>>(x, out);
}

// round 17
// speedup vs baseline: 1.3841x; 1.1030x over previous
#include <cuda_runtime.h>
#include <cuda_fp16.h>
#include <math.h>
#include <stdint.h>

#define NT 128
#define BUF 8192                       // one 64x64 fp16 buffer: 64 rows x 128B
#define SMEM_TOTAL (5*BUF + 64)
// buffers: 0,1 = Y splits ; 2,3 = Z splits ; 4 = T (single split; holds coarse A first)

__device__ __forceinline__ uint32_t swz(uint32_t b) { return b ^ ((b >> 3) & 0x70); }

__device__ __forceinline__ uint32_t smem_u32(const void* p) {
    uint32_t a;
    asm("{ .reg .u64 t; cvta.to.shared.u64 t, %1; cvt.u32.u64 %0, t; }" : "=r"(a) : "l"(p));
    return a;
}

__device__ __forceinline__ void ldsm4(uint32_t* r, uint32_t addr) {
    asm volatile("ldmatrix.sync.aligned.m8n8.x4.shared.b16 {%0,%1,%2,%3}, [%4];"
                 : "=r"(r[0]), "=r"(r[1]), "=r"(r[2]), "=r"(r[3]) : "r"(addr));
}

__device__ __forceinline__ void mma16816(float* c, const uint32_t* a,
                                         uint32_t b0, uint32_t b1) {
    asm volatile("mma.sync.aligned.m16n8k16.row.col.f32.f16.f16.f32 "
                 "{%0,%1,%2,%3}, {%4,%5,%6,%7}, {%8,%9}, {%0,%1,%2,%3};"
                 : "+f"(c[0]), "+f"(c[1]), "+f"(c[2]), "+f"(c[3])
                 : "r"(a[0]), "r"(a[1]), "r"(a[2]), "r"(a[3]), "r"(b0), "r"(b1));
}

// fp32 -> 2-term fp16 split
__device__ __forceinline__ void split2(float v, __half& h1, __half& h2) {
    h1 = __float2half_rn(v);
    h2 = __float2half_rn(v - __half2float(h1));
}
__device__ __forceinline__ uint32_t packh(__half a, __half b) {
    __half2 t; t.x = a; t.y = b;
    return *reinterpret_cast<uint32_t*>(&t);
}

// ---- 2-product MMA phase ----
// FORM 0: coarse-A x full-B :  acc = a1@(b1+b2)   (A ldsm from a1 only)
// FORM 1: full-A x coarse-B :  acc = (a1+a2)@b1   (B ldsm from b1 only)
// Both 64 warp-MMA, 24 ldsm.x4.
template <int FORM>
__device__ __forceinline__ void mma_phase(uint32_t sbase,
                                          int a1, int a2, int b1, int b2,
                                          int wm, int wn, int lane,
                                          float acc[2][4][4])
{
#pragma unroll
    for (int mt = 0; mt < 2; ++mt)
#pragma unroll
        for (int j = 0; j < 4; ++j)
#pragma unroll
            for (int q = 0; q < 4; ++q) acc[mt][j][q] = 0.0f;

    const int arow = wm * 32 + (lane & 15);
    const int acol = (lane >> 4) * 16;
    const int bl = lane & 7;
    const int bg = lane >> 3;
    const uint32_t bcol = (uint32_t)((bg >> 1) * 32 + (bg & 1) * 16);

#pragma unroll
    for (int ktp = 0; ktp < 2; ++ktp) {
        uint32_t A1[2][2][4], A2[2][2][4];
#pragma unroll
        for (int mt = 0; mt < 2; ++mt)
#pragma unroll
            for (int ktl = 0; ktl < 2; ++ktl) {
                uint32_t rel = swz((uint32_t)((arow + mt * 16) * 128 +
                                              ktp * 64 + ktl * 32 + acol));
                ldsm4(A1[mt][ktl], sbase + a1 + rel);
                if (FORM == 1) ldsm4(A2[mt][ktl], sbase + a2 + rel);
            }
#pragma unroll
        for (int j = 0; j < 4; ++j) {
            const uint32_t rowb = (uint32_t)((wn * 32 + j * 8 + bl) * 128);
            uint32_t rel = swz(rowb + ktp * 64 + bcol);
            uint32_t Bx[4], Cx[4];
            ldsm4(Bx, sbase + b1 + rel);   // regs 0,1 = kt_lo ; 2,3 = kt_hi
            if (FORM == 0) ldsm4(Cx, sbase + b2 + rel);
#pragma unroll
            for (int ktl = 0; ktl < 2; ++ktl) {
#pragma unroll
                for (int mt = 0; mt < 2; ++mt) {
                    mma16816(acc[mt][j], A1[mt][ktl], Bx[2*ktl], Bx[2*ktl+1]);
                    if (FORM == 0)
                        mma16816(acc[mt][j], A1[mt][ktl], Cx[2*ktl], Cx[2*ktl+1]);
                    else
                        mma16816(acc[mt][j], A2[mt][ktl], Bx[2*ktl], Bx[2*ktl+1]);
                }
            }
        }
    }
}

// ---- epilogue ----
// MODE 0: dst = D          MODE 1: dst = 1.5I - 0.5 D    MODE 2: gmem O = scale*D
// NS 2: store both splits to d1,d2    NS 1: store single fp16 round to d1 only
template <int MODE, int NS>
__device__ __forceinline__ void epi_phase(char* smem, int d1, int d2,
                                          float* __restrict__ O, float scale,
                                          int wm, int wn, int lane,
                                          const float acc[2][4][4])
{
    const int gr = lane >> 2, qp = lane & 3;
#pragma unroll
    for (int mt = 0; mt < 2; ++mt)
#pragma unroll
    for (int j = 0; j < 4; ++j) {
        const int colb = wn * 32 + j * 8 + 2 * qp;
#pragma unroll
        for (int half = 0; half < 2; ++half) {
            const int row = wm * 32 + mt * 16 + gr + half * 8;
            float v0 = acc[mt][j][half * 2 + 0];
            float v1 = acc[mt][j][half * 2 + 1];
            if (MODE == 1) {
                v0 = (colb     == row ? 1.5f : 0.0f) - 0.5f * v0;
                v1 = (colb + 1 == row ? 1.5f : 0.0f) - 0.5f * v1;
            }
            if (MODE == 2) {
                *(float2*)(O + row * 64 + colb) = make_float2(v0 * scale, v1 * scale);
            } else if (NS == 1) {
                uint32_t off = swz((uint32_t)(row * 128 + colb * 2));
                *(uint32_t*)(smem + d1 + off) =
                    packh(__float2half_rn(v0), __float2half_rn(v1));
            } else {
                __half p0, q0, p1, q1;
                split2(v0, p0, q0);
                split2(v1, p1, q1);
                uint32_t off = swz((uint32_t)(row * 128 + colb * 2));
                *(uint32_t*)(smem + d1 + off) = packh(p0, p1);
                *(uint32_t*)(smem + d2 + off) = packh(q0, q1);
            }
        }
    }
}

// disjoint GEMM: dest intersects no source -> NO mid-barrier
template <int MODE, int NS, int FORM>
__device__ __forceinline__ void gemm_disjoint(uint32_t sbase, char* smem,
                                              int a1, int a2, int b1, int b2,
                                              int d1, int d2,
                                              float* __restrict__ O, float scale,
                                              int wm, int wn, int lane)
{
    float acc[2][4][4];
    __syncthreads();            // previous epilogue writes visible
    mma_phase<FORM>(sbase, a1, a2, b1, b2, wm, wn, lane, acc);
    epi_phase<MODE, NS>(smem, d1, d2, O, scale, wm, wn, lane, acc);
}

// in-place GEMM (dest aliases a source): opening + mid barrier
template <int MODE, int NS, int FORM>
__device__ __forceinline__ void gemm_inplace(uint32_t sbase, char* smem,
                                             int a1, int a2, int b1, int b2,
                                             int d1, int d2,
                                             float* __restrict__ O, float scale,
                                             int wm, int wn, int lane)
{
    float acc[2][4][4];
    __syncthreads();            // previous epilogue writes visible
    mma_phase<FORM>(sbase, a1, a2, b1, b2, wm, wn, lane, acc);
    __syncthreads();            // all reads done before overwrite
    epi_phase<MODE, NS>(smem, d1, d2, O, scale, wm, wn, lane, acc);
}

// in-place GEMM with NO opening barrier: valid when the immediately preceding
// epilogue wrote buffers disjoint from this GEMM's sources.
template <int MODE, int NS, int FORM>
__device__ __forceinline__ void gemm_inplace_noopen(uint32_t sbase, char* smem,
                                                    int a1, int a2, int b1, int b2,
                                                    int d1, int d2,
                                                    float* __restrict__ O, float scale,
                                                    int wm, int wn, int lane)
{
    float acc[2][4][4];
    mma_phase<FORM>(sbase, a1, a2, b1, b2, wm, wn, lane, acc);
    __syncthreads();            // all reads done before overwrite
    epi_phase<MODE, NS>(smem, d1, d2, O, scale, wm, wn, lane, acc);
}

__global__ void __launch_bounds__(NT, 4)
isqrtm_hmma_kernel(const float* __restrict__ x, float* __restrict__ out)
{
    extern __shared__ char smem[];
    const uint32_t sbase = smem_u32(smem);
    float* red = (float*)(smem + 5 * BUF);

    const int tid = threadIdx.x;
    const int wid = tid >> 5, lane = tid & 31;
    const int wm = wid >> 1, wn = wid & 1;
    const int b = blockIdx.x;
    const float* X = x + (size_t)b * 4096;
    float* O = out + (size_t)b * 4096;

    // ---- trace(X) ----
    float tr = (tid < 64) ? __ldg(X + tid * 65) : 0.0f;
#pragma unroll
    for (int o = 16; o; o >>= 1) tr += __shfl_xor_sync(0xFFFFFFFFu, tr, o);
    if (lane == 0) red[wid] = tr;
    __syncthreads();
    const float normA = red[0] + red[1];
    const float inv = 1.0f / normA;
    const float sq  = sqrtf(normA);
    __syncthreads();

    // ---- prologue: coarse A -> buf 4 ; Z = 1.5I - 0.5A -> bufs 2,3 (2 splits) ----
    {
        const int r  = tid >> 1;
        const int c0 = (tid & 1) * 32;
#pragma unroll
        for (int q = 0; q < 16; ++q) {
            const int c = c0 + 2 * q;
            float2 f = *(const float2*)(X + r * 64 + c);
            float a0 = f.x * inv, a1 = f.y * inv;
            float z0 = (c     == r ? 1.5f : 0.0f) - 0.5f * a0;
            float z1 = (c + 1 == r ? 1.5f : 0.0f) - 0.5f * a1;
            uint32_t off = swz((uint32_t)(r * 128 + c * 2));
            *(uint32_t*)(smem + 4 * BUF + off) =
                packh(__float2half_rn(a0), __float2half_rn(a1));
            __half p0, s0, p1, s1;
            split2(z0, p0, s0); split2(z1, p1, s1);
            *(uint32_t*)(smem + 2 * BUF + off) = packh(p0, p1);
            *(uint32_t*)(smem + 3 * BUF + off) = packh(s0, s1);
        }
    }

    // ---- Newton-Schulz chain: uniform 2-product GEMMs ----
    // Y = A @ Z : coarse-A(4) x full-Z(2,3) -> Y(0,1).  dest disjoint.
    gemm_disjoint<0,2,0>(sbase, smem, 4*BUF, 0, 2*BUF, 3*BUF, 0*BUF, 1*BUF,
                         O, 0.f, wm, wn, lane);
#pragma unroll 1
    for (int it = 0; it < 3; ++it) {
        // T = 1.5I - 0.5 Z@Y : coarse-Z(2) x full-Y(0,1) -> T(4) single split.
        // dest 4 disjoint from sources {2,0,1}; prior reads of buf4 (as A/T)
        // are ordered by this opening barrier.
        gemm_disjoint<1,1,0>(sbase, smem, 2*BUF, 0, 0*BUF, 1*BUF, 4*BUF, 0,
                             O, 0.f, wm, wn, lane);
        // Y = Y @ T : full-Y(0,1) x coarse-T(4) -> Y(0,1) in-place.
        // opening bar: prev epi wrote 4 which we read.
        gemm_inplace<0,2,1>(sbase, smem, 0*BUF, 1*BUF, 4*BUF, 0, 0*BUF, 1*BUF,
                            O, 0.f, wm, wn, lane);
        // Z = T @ Z : coarse-T(4) x full-Z(2,3) -> Z(2,3) in-place (B-side).
        // prev epi wrote only 0,1 (disjoint from sources {4,2,3}) -> no opening bar.
        gemm_inplace_noopen<0,2,0>(sbase, smem, 4*BUF, 0, 2*BUF, 3*BUF, 2*BUF, 3*BUF,
                                   O, 0.f, wm, wn, lane);
    }
    // final T = 1.5I - 0.5 Z@Y  (single split)
    gemm_disjoint<1,1,0>(sbase, smem, 2*BUF, 0, 0*BUF, 1*BUF, 4*BUF, 0,
                         O, 0.f, wm, wn, lane);
    // out = sqrt(normA) * (Y @ T) : full-Y x coarse-T, gmem dest
    gemm_disjoint<2,2,1>(sbase, smem, 0*BUF, 1*BUF, 4*BUF, 0, 0, 0,
                         O, sq, wm, wn, lane);
}

extern "C" void kernel_launch(void* const* d_in, const int* in_sizes, int n_in,
                              void* d_out, int out_size)
{
    const float* x = (const float*)d_in[0];
    float* out = (float*)d_out;
    const int batches = in_sizes[0] / 4096;

    cudaFuncSetAttribute(isqrtm_hmma_kernel,
                         cudaFuncAttributeMaxDynamicSharedMemorySize, SMEM_TOTAL);
    isqrtm_hmma_kernel<<<batches, NT, SMEM_TOTAL>>>(x, out);
}